// round 12
// baseline (speedup 1.0000x reference)
#include <cuda_runtime.h>
#include <cuda_bf16.h>
#include <cstdint>

// PostProcessor3D: threshold(0.9) -> 5x5x5 maxpool(stride1,pad2) -> strict peak mask.
// In: [64,512,512] f32.  Out: [64,512,512] f32.
//
// Block (64,4)=256 threads, EIGHT W-cols per thread (two float4 halves A/B),
// full W=512 x 4 H rows, marching 36 planes of a 32-deep D chunk in PAIRS.
// Grid 128x2 = 256 blocks, 2 blocks/SM (launch_bounds(256,2) -> 128 regs).
//
// Raw-domain max (thr commutes with max; pads are 0). Threshold at emission:
//   out(od) = (cen==M3d && cen>THRESH) ? cen : 0.
//
// RACE-FREE pair pipeline (NBUF=6, lookahead 2, issue BEFORE wait):
//   iter k (p=2k): issue p+2 -> buf (p+2)%6, p+3 -> (p+3)%6; wait_group 2
//   (p, p+1 complete); BAR; compute p, p+1.
// Safety: iter-k writes hit bufs (p-4)%6,(p-3)%6. The slowest concurrent
// reader is bounded by BAR(k-1) => at worst computing planes p-2, p-1
// (bufs (p-2)%6,(p-1)%6) — disjoint. [Triple-schedule violated this: R10/R11 bug.]
// Off-range planes commit EMPTY groups.

#define Wd 512
#define Hd 512
#define Dd 64
#define TH 4
#define LR 8
#define DCH 32
#define NP (DCH + 4)        // 36 (even)
#define PSZ (Hd * Wd)
#define THRESH 0.9f
#define BUFSZ (LR * Wd)     // 4096 floats per buffer
#define NBUF 6

__device__ __forceinline__ void cp_async16(uint32_t dst, const void* src, int src_bytes) {
    asm volatile("cp.async.cg.shared.global [%0], [%1], 16, %2;\n"
                 :: "r"(dst), "l"(src), "r"(src_bytes));
}
__device__ __forceinline__ void cp_commit() {
    asm volatile("cp.async.commit_group;\n");
}
__device__ __forceinline__ void cp_wait2() {
    asm volatile("cp.async.wait_group 2;\n");
}
__device__ __forceinline__ void cp_wait0() {
    asm volatile("cp.async.wait_group 0;\n");
}

__device__ __forceinline__ float4 fmax4(float4 a, float4 b) {
    return make_float4(fmaxf(a.x, b.x), fmaxf(a.y, b.y),
                       fmaxf(a.z, b.z), fmaxf(a.w, b.w));
}

// W-window-5 max for 4 cols given h(c..c+3) and neighbors L2,L1 (c-2,c-1), R4,R5 (c+4,c+5)
__device__ __forceinline__ float4 wmax5(float L2, float L1, float4 h, float R4, float R5) {
    float m01 = fmaxf(h.x, h.y), m12 = fmaxf(h.y, h.z), m23 = fmaxf(h.z, h.w);
    float4 m;
    m.x = fmaxf(fmaxf(L2, L1), fmaxf(m01, h.z));
    m.y = fmaxf(L1, fmaxf(m01, m23));
    m.z = fmaxf(fmaxf(m01, m23), R4);
    m.w = fmaxf(fmaxf(m12, h.w), fmaxf(R4, R5));
    return m;
}

extern __shared__ float vsm[];   // [NBUF][LR][512] raw planes

__global__ __launch_bounds__(256, 2)
void peak3d_kernel(const float* __restrict__ in, float* __restrict__ out) {
    const int tx   = threadIdx.x;          // 0..63
    const int ty   = threadIdx.y;          // 0..3
    const int lane = tx & 31;
    const int c    = tx << 3;              // 8 cols per thread
    const int h0   = blockIdx.x * TH;
    const int d0   = blockIdx.y * DCH;

    const bool edgeL    = (lane == 0);
    const bool edgeR    = (lane == 31);
    const bool haveEdge = (edgeL && tx != 0) || (edgeR && tx != 63);
    const int  ec       = edgeL ? (c - 2) : (c + 8);

    // this thread copies loaded-rows ty and ty+4 of strip [h0-2, h0+5], 8 cols
    const int  gh1 = h0 - 2 + ty;
    const int  gh2 = h0 + 2 + ty;
    const bool ok1 = ((unsigned)gh1 < (unsigned)Hd);
    const bool ok2 = (gh2 < Hd);

    const float* g1 = in + (size_t)(ok1 ? gh1 : 0) * Wd + c;
    const float* g2 = in + (size_t)(ok2 ? gh2 : 0) * Wd + c;

    const uint32_t sbase = (uint32_t)__cvta_generic_to_shared(vsm);
    const uint32_t dst1  = sbase + (uint32_t)(ty * Wd + c) * 4u;
    const uint32_t dst2  = sbase + (uint32_t)((ty + 4) * Wd + c) * 4u;
    const uint32_t BUFB  = BUFSZ * 4u;

    // issue async copies for plane pf (dl = d0-2+pf) into buf pf%NBUF.
    // pf >= NP: EMPTY commit group (keeps wait counts aligned, no writes).
    auto issue = [&](int pf) {
        if (pf < NP) {
            int  dl  = d0 - 2 + pf;
            bool dok = ((unsigned)dl < (unsigned)Dd);
            int  dlc = dok ? dl : 0;
            uint32_t boff = (uint32_t)(pf % NBUF) * BUFB;
            const float* s1 = g1 + (size_t)dlc * PSZ;
            const float* s2 = g2 + (size_t)dlc * PSZ;
            int b1 = (ok1 && dok) ? 16 : 0;
            int b2 = (ok2 && dok) ? 16 : 0;
            cp_async16(dst1 + boff,      s1,     b1);
            cp_async16(dst1 + boff + 16, s1 + 4, b1);
            cp_async16(dst2 + boff,      s2,     b2);
            cp_async16(dst2 + boff + 16, s2 + 4, b2);
        }
        cp_commit();
    };

    issue(0);
    issue(1);

    // rings (raw domain), per half
    float4 z = make_float4(0.f, 0.f, 0.f, 0.f);
    float4 rA1 = z, rA2 = z, rA3 = z, rA4 = z, cA1 = z, cA2 = z;
    float4 rB1 = z, rB2 = z, rB3 = z, rB4 = z, cB1 = z, cB2 = z;

    float* outp = out + (size_t)d0 * PSZ + (size_t)(h0 + ty) * Wd + c;

    auto plane = [&](const float* vb, bool emit) {
        const float* vr = vb + ty * Wd + c;
        // H-max over 5 rows, both halves
        float4 a0 = *(const float4*)(vr);        float4 b0 = *(const float4*)(vr + 4);
        float4 a1 = *(const float4*)(vr + 512);  float4 b1 = *(const float4*)(vr + 516);
        float4 a2 = *(const float4*)(vr + 1024); float4 b2 = *(const float4*)(vr + 1028);
        float4 a3 = *(const float4*)(vr + 1536); float4 b3 = *(const float4*)(vr + 1540);
        float4 a4 = *(const float4*)(vr + 2048); float4 b4 = *(const float4*)(vr + 2052);
        float4 cenA = a2, cenB = b2;
        float4 hA = fmax4(fmax4(fmax4(a0, a1), fmax4(a2, a3)), a4);
        float4 hB = fmax4(fmax4(fmax4(b0, b1), fmax4(b2, b3)), b4);

        float2 eh = make_float2(0.f, 0.f);
        if (haveEdge) {
            const float* ep = vb + ty * Wd + ec;
            float2 e0 = *(const float2*)(ep);
            float2 e1 = *(const float2*)(ep + 512);
            float2 e2 = *(const float2*)(ep + 1024);
            float2 e3 = *(const float2*)(ep + 1536);
            float2 e4 = *(const float2*)(ep + 2048);
            eh.x = fmaxf(fmaxf(fmaxf(e0.x, e1.x), fmaxf(e2.x, e3.x)), e4.x);
            eh.y = fmaxf(fmaxf(fmaxf(e0.y, e1.y), fmaxf(e2.y, e3.y)), e4.y);
        }

        // neighbor exchange: A's left from lane-1's B top, B's right from lane+1's A bottom
        float l2 = __shfl_up_sync(0xffffffffu, hB.z, 1);
        float l1 = __shfl_up_sync(0xffffffffu, hB.w, 1);
        float r4 = __shfl_down_sync(0xffffffffu, hA.x, 1);
        float r5 = __shfl_down_sync(0xffffffffu, hA.y, 1);
        if (edgeL) { l2 = eh.x; l1 = eh.y; }   // 0 at global W edge
        if (edgeR) { r4 = eh.x; r5 = eh.y; }

        float4 mA = wmax5(l2, l1, hA, hB.x, hB.y);
        float4 mB = wmax5(hA.z, hA.w, hB, r4, r5);

        if (emit) {
            float4 M3A = fmax4(fmax4(fmax4(rA4, rA3), fmax4(rA2, rA1)), mA);
            float4 M3B = fmax4(fmax4(fmax4(rB4, rB3), fmax4(rB2, rB1)), mB);
            float4 oA, oB;
            oA.x = (cA2.x == M3A.x && cA2.x > THRESH) ? cA2.x : 0.f;
            oA.y = (cA2.y == M3A.y && cA2.y > THRESH) ? cA2.y : 0.f;
            oA.z = (cA2.z == M3A.z && cA2.z > THRESH) ? cA2.z : 0.f;
            oA.w = (cA2.w == M3A.w && cA2.w > THRESH) ? cA2.w : 0.f;
            oB.x = (cB2.x == M3B.x && cB2.x > THRESH) ? cB2.x : 0.f;
            oB.y = (cB2.y == M3B.y && cB2.y > THRESH) ? cB2.y : 0.f;
            oB.z = (cB2.z == M3B.z && cB2.z > THRESH) ? cB2.z : 0.f;
            oB.w = (cB2.w == M3B.w && cB2.w > THRESH) ? cB2.w : 0.f;
            *(float4*)outp = oA;
            *(float4*)(outp + 4) = oB;
            outp += PSZ;
        }

        rA4 = rA3; rA3 = rA2; rA2 = rA1; rA1 = mA;
        rB4 = rB3; rB3 = rB2; rB2 = rB1; rB1 = mB;
        cA2 = cA1; cA1 = cenA;
        cB2 = cB1; cB1 = cenB;
    };

    #pragma unroll 3
    for (int k = 0; k < NP / 2; ++k) {
        const int p = 2 * k;

        issue(p + 2);       // -> buf (p-4)%6 ; slowest reader is at (p-2),(p-1): disjoint
        issue(p + 3);       // -> buf (p-3)%6

        cp_wait2();         // planes p, p+1 complete (p+2, p+3 may pend)
        __syncthreads();    // all threads' copies of p, p+1 visible

        plane(vsm + ( p      % NBUF) * BUFSZ, p     >= 4);
        plane(vsm + ((p + 1) % NBUF) * BUFSZ, p + 1 >= 4);
    }

    cp_wait0();   // drain trailing groups before exit
}

extern "C" void kernel_launch(void* const* d_in, const int* in_sizes, int n_in,
                              void* d_out, int out_size) {
    (void)in_sizes; (void)n_in; (void)out_size;
    const float* in = (const float*)d_in[0];
    float* out = (float*)d_out;

    const int smem_bytes = NBUF * BUFSZ * (int)sizeof(float);   // 98304
    cudaFuncSetAttribute(peak3d_kernel,
                         cudaFuncAttributeMaxDynamicSharedMemorySize, smem_bytes);

    dim3 block(64, 4);                  // 256 threads, 8 cols/thread
    dim3 grid(Hd / TH, Dd / DCH);       // 128 x 2 = 256 blocks (2/SM resident)
    peak3d_kernel<<<grid, block, smem_bytes>>>(in, out);
}